// round 17
// baseline (speedup 1.0000x reference)
#include <cuda_runtime.h>
#include <cuda_bf16.h>
#include <cstdint>
#include <math.h>

#define FIELD 39
#define EMBD 8
#define MAXB 16384
#define D0 312
#define D0P 320
#define D1 512
#define D2 256
#define D3 128

#define KW0 (D0P / 2)    // 160
#define KW1 (D1 / 2)     // 256
#define KW2 (D2 / 2)     // 128

// Scratch (allocation-free rule). Activations packed bf16x2, k-contiguous.
__device__ float    g_li[MAXB];
__device__ unsigned g_h0[MAXB * KW0];
__device__ unsigned g_h1[MAXB * KW1];
__device__ unsigned g_h2[MAXB * KW2];
// packed weights, layout [N][KW]
__device__ unsigned g_w0p[D1 * KW0];
__device__ unsigned g_w1p[D2 * KW1];
__device__ unsigned g_w2p[D3 * KW2];

__device__ __forceinline__ unsigned pack_bf2(float a, float b) {
    __nv_bfloat162 p = __floats2bfloat162_rn(a, b);
    return *(unsigned*)&p;
}

// ---------------------------------------------------------------------------
// 1a. gather kernel (verbatim R16)
// ---------------------------------------------------------------------------
__global__ __launch_bounds__(256, 8) void gather_k(
    const int* __restrict__ ids, const float* __restrict__ emb, int B)
{
    int idx = blockIdx.x * 256 + threadIdx.x;
    if (idx >= B * 40) return;
    int b = idx / 40, f = idx % 40;
    uint4 o;
    if (f < FIELD) {
        int id = ids[b * FIELD + f];
        const float4* e = (const float4*)(emb + (size_t)id * EMBD);
        float4 e0 = e[0];
        float4 e1 = e[1];
        o.x = pack_bf2(e0.x, e0.y);
        o.y = pack_bf2(e0.z, e0.w);
        o.z = pack_bf2(e1.x, e1.y);
        o.w = pack_bf2(e1.z, e1.w);
    } else {
        o = make_uint4(0u, 0u, 0u, 0u);
    }
    *(uint4*)(g_h0 + (size_t)b * KW0 + f * 4) = o;
}

// ---------------------------------------------------------------------------
// 1b. li (32 samples/block, coalesced staging) + pack (transposed, coalesced)
//     roles: [0, liB): li ; [liB, liB+160): pack
// ---------------------------------------------------------------------------
#define PACK_BLKS 160   // W0: 5x16=80, W1: 8x8=64, W2: 4x4=16

__global__ __launch_bounds__(256) void lipack_k(
    const int* __restrict__ ids, const float* __restrict__ vals,
    const float* __restrict__ FM_W, const float* __restrict__ FM_V,
    const float* __restrict__ FM_B,
    const float* __restrict__ W0, const float* __restrict__ W1,
    const float* __restrict__ W2, int B, int liB)
{
    const int bid = blockIdx.x;
    const int t = threadIdx.x;

    if (bid < liB) {
        // ---- li role: 32 samples per block ----
        __shared__ float Vi[FIELD * 64];
        __shared__ float Ss[FIELD * FIELD];
        __shared__ float vsm[32 * 40];
        __shared__ float lwsm[32 * 40];
        for (int idx = t; idx < FIELD * 64; idx += 256) {
            int i = idx / 64, r = idx % 64;
            long long off = (long long)i * (51000LL * 64LL) + r;
            Vi[idx] = FM_V[off];
        }
        __syncthreads();
        for (int idx = t; idx < FIELD * FIELD; idx += 256) {
            int i = idx / FIELD, j = idx % FIELD;
            float s = 0.f;
            if (j > i) {
#pragma unroll
                for (int e = 0; e < EMBD; e++)
                    s += Vi[i * 64 + (j & 7) * 8 + e] * Vi[j * 64 + (i & 7) * 8 + e];
            }
            Ss[idx] = s;
        }
        __syncthreads();

        // coalesced stage of 32*39 ids/vals
        int sbase = bid * 32;
        int ebase = sbase * FIELD;
        for (int e = t; e < 32 * FIELD; e += 256) {
            int s = e / FIELD, f = e % FIELD;
            int id = ids[ebase + e];
            float val = vals[ebase + e];
            vsm[s * 40 + f] = val;
            lwsm[s * 40 + f] = FM_W[id] * val;
        }
        __syncthreads();

        // 8 threads per sample
        int s = t >> 3, sub = t & 7;
        float p = 0.f;
        for (int f = sub; f < FIELD; f += 8) p += lwsm[s * 40 + f];
        for (int i = sub; i < FIELD; i += 8) {
            float ti = 0.f;
            for (int j = i + 1; j < FIELD; j++)
                ti += Ss[i * FIELD + j] * vsm[s * 40 + j];
            p += vsm[s * 40 + i] * ti;
        }
        p += __shfl_xor_sync(0xffffffffu, p, 1);
        p += __shfl_xor_sync(0xffffffffu, p, 2);
        p += __shfl_xor_sync(0xffffffffu, p, 4);
        if (sub == 0) g_li[sbase + s] = p + FM_B[0];
    } else {
        // ---- pack role: 32x32 (kp, n) tile with smem transpose ----
        __shared__ unsigned tile[32][33];
        int b2 = bid - liB;
        const float* W; unsigned* G; int KW, N, K, kp0, n0;
        if (b2 < 80)       { W = W0; G = g_w0p; KW = KW0; N = D1; K = D0;
                             kp0 = (b2 % 5) * 32;  n0 = (b2 / 5) * 32; }
        else if (b2 < 144) { b2 -= 80; W = W1; G = g_w1p; KW = KW1; N = D2; K = D1;
                             kp0 = (b2 % 8) * 32;  n0 = (b2 / 8) * 32; }
        else               { b2 -= 144; W = W2; G = g_w2p; KW = KW2; N = D3; K = D2;
                             kp0 = (b2 % 4) * 32;  n0 = (b2 / 4) * 32; }
        int tx = t & 31, ty = t >> 5;
#pragma unroll
        for (int i = 0; i < 4; i++) {
            int kp = kp0 + ty * 4 + i;
            int k = 2 * kp;
            int n = n0 + tx;
            float a = (k     < K) ? W[(size_t)k * N + n]       : 0.f;
            float c = (k + 1 < K) ? W[(size_t)(k + 1) * N + n] : 0.f;
            tile[ty * 4 + i][tx] = pack_bf2(a, c);
        }
        __syncthreads();
#pragma unroll
        for (int i = 0; i < 4; i++) {
            int n = n0 + ty * 4 + i;
            int kp = kp0 + tx;
            G[(size_t)n * KW + kp] = tile[tx][ty * 4 + i];
        }
    }
}

// ---------------------------------------------------------------------------
// HMMA machinery (verbatim R7): 3 stages, BM=64, BN=128, BK=32, 8 warps,
// warp tile 32x32, distance-2 prefetch, static smem.
// ---------------------------------------------------------------------------
#define SSTG 3
#define ASTG (64 * 16)
#define BSTG (128 * 16)

__device__ __forceinline__ void ldmx4(unsigned &r0, unsigned &r1, unsigned &r2,
                                      unsigned &r3, unsigned addr) {
    asm volatile("ldmatrix.sync.aligned.m8n8.x4.shared.b16 {%0,%1,%2,%3}, [%4];"
                 : "=r"(r0), "=r"(r1), "=r"(r2), "=r"(r3) : "r"(addr));
}

__device__ __forceinline__ void mma_bf16(float* c, const unsigned* a, const unsigned* b) {
    asm volatile(
        "mma.sync.aligned.m16n8k16.row.col.f32.bf16.bf16.f32 "
        "{%0,%1,%2,%3}, {%4,%5,%6,%7}, {%8,%9}, {%0,%1,%2,%3};"
        : "+f"(c[0]), "+f"(c[1]), "+f"(c[2]), "+f"(c[3])
        : "r"(a[0]), "r"(a[1]), "r"(a[2]), "r"(a[3]), "r"(b[0]), "r"(b[1]));
}

struct Frag { float acc[2][4][4]; };

__device__ __forceinline__ void tile_compute(
    unsigned aOff, unsigned bOff, int lane, int wm, int wn, Frag &F)
{
    const int lrow = lane & 15;
    const int lsel = lane >> 4;
#pragma unroll
    for (int s = 0; s < 2; s++) {
        unsigned a[2][4], b[4][2];
        int lc = 2 * s + lsel;
#pragma unroll
        for (int p = 0; p < 2; p++) {
            int n = wn + p * 16 + lrow;
            int pc = lc ^ ((n >> 1) & 3);
            unsigned r0, r1, r2, r3;
            ldmx4(r0, r1, r2, r3, bOff + (n * 16 + pc * 4) * 4);
            b[2 * p][0] = r0;  b[2 * p + 1][0] = r1;
            b[2 * p][1] = r2;  b[2 * p + 1][1] = r3;
        }
#pragma unroll
        for (int mt = 0; mt < 2; mt++) {
            int m = wm + mt * 16 + lrow;
            int pc = lc ^ ((m >> 1) & 3);
            ldmx4(a[mt][0], a[mt][1], a[mt][2], a[mt][3],
                  aOff + (m * 16 + pc * 4) * 4);
        }
#pragma unroll
        for (int mt = 0; mt < 2; mt++)
#pragma unroll
            for (int nt = 0; nt < 4; nt++)
                mma_bf16(F.acc[mt][nt], a[mt], b[nt]);
    }
}

__device__ __forceinline__ void load_B(
    const unsigned* __restrict__ Wp, int KW, int bn, unsigned bBase,
    int t, int st, int kt)
{
    int kw0 = kt * 16;
#pragma unroll
    for (int i = 0; i < 2; i++) {
        int idx = t + 256 * i;
        int n = idx >> 2, c = idx & 3;
        int pc = c ^ ((n >> 1) & 3);
        const unsigned* g = Wp + (size_t)(bn + n) * KW + kw0 + c * 4;
        unsigned s = bBase + (st * BSTG + n * 16 + pc * 4) * 4;
        asm volatile("cp.async.cg.shared.global [%0], [%1], 16;" :: "r"(s), "l"(g));
    }
}

__device__ __forceinline__ void load_A(
    const unsigned* __restrict__ A, int KW, int bm, unsigned aBase,
    int t, int st, int kt)
{
    int m = t >> 2, c = t & 3;
    int pc = c ^ ((m >> 1) & 3);
    const unsigned* g = A + (size_t)(bm + m) * KW + kt * 16 + c * 4;
    unsigned s = aBase + (st * ASTG + m * 16 + pc * 4) * 4;
    asm volatile("cp.async.cg.shared.global [%0], [%1], 16;" :: "r"(s), "l"(g));
}

// ---------------------------------------------------------------------------
// 2. GEMM + bias + ReLU -> packed bf16x2 output (layers 0 & 1) [verbatim R7]
// ---------------------------------------------------------------------------
__global__ __launch_bounds__(256, 3) void gemm_mid(
    const unsigned* __restrict__ A, const unsigned* __restrict__ Wp,
    const float* __restrict__ bias, unsigned* __restrict__ C,
    int N, int KW)
{
    __shared__ unsigned As[SSTG * ASTG];
    __shared__ unsigned Bs[SSTG * BSTG];

    const int t = threadIdx.x;
    const int lane = t & 31;
    const int warp = t >> 5;
    const int wm = (warp >> 2) * 32;
    const int wn = (warp & 3) * 32;
    const int bm = blockIdx.y * 64;
    const int bn = blockIdx.x * 128;
    const unsigned aBase = (unsigned)__cvta_generic_to_shared(As);
    const unsigned bBase = (unsigned)__cvta_generic_to_shared(Bs);
    const int nk = KW >> 4;

    Frag F = {};

    load_A(A, KW, bm, aBase, t, 0, 0);
    load_B(Wp, KW, bn, bBase, t, 0, 0);
    asm volatile("cp.async.commit_group;" ::: "memory");
    load_A(A, KW, bm, aBase, t, 1, 1);
    load_B(Wp, KW, bn, bBase, t, 1, 1);
    asm volatile("cp.async.commit_group;" ::: "memory");

    for (int kt = 0; kt < nk; kt++) {
        asm volatile("cp.async.wait_group 1;" ::: "memory");
        __syncthreads();

        int pf = kt + 2;
        if (pf < nk) {
            load_A(A, KW, bm, aBase, t, pf % SSTG, pf);
            load_B(Wp, KW, bn, bBase, t, pf % SSTG, pf);
        }
        asm volatile("cp.async.commit_group;" ::: "memory");

        tile_compute(aBase + (kt % SSTG) * ASTG * 4,
                     bBase + (kt % SSTG) * BSTG * 4, lane, wm, wn, F);
    }

    const int r = lane >> 2, cc = lane & 3;
    const int NW = N >> 1;
#pragma unroll
    for (int nt = 0; nt < 4; nt++) {
        int col = bn + wn + nt * 8 + 2 * cc;
        float b0 = bias[col], b1 = bias[col + 1];
        int cw = col >> 1;
#pragma unroll
        for (int mt = 0; mt < 2; mt++) {
            int row0 = bm + wm + mt * 16 + r;
            unsigned o0 = pack_bf2(fmaxf(F.acc[mt][nt][0] + b0, 0.f),
                                   fmaxf(F.acc[mt][nt][1] + b1, 0.f));
            unsigned o1 = pack_bf2(fmaxf(F.acc[mt][nt][2] + b0, 0.f),
                                   fmaxf(F.acc[mt][nt][3] + b1, 0.f));
            C[(size_t)row0 * NW + cw] = o0;
            C[(size_t)(row0 + 8) * NW + cw] = o1;
        }
    }
}

// ---------------------------------------------------------------------------
// 3. last GEMM fused with output head (verbatim R7)
// ---------------------------------------------------------------------------
__global__ __launch_bounds__(256, 3) void gemm_last_head(
    const unsigned* __restrict__ A, const unsigned* __restrict__ Wp,
    const float* __restrict__ bias, const float* __restrict__ outW,
    const float* __restrict__ outB, float* __restrict__ out, int KW)
{
    __shared__ unsigned As[SSTG * ASTG];
    __shared__ unsigned Bs[SSTG * BSTG];
    __shared__ float red[64][4];

    const int t = threadIdx.x;
    const int lane = t & 31;
    const int warp = t >> 5;
    const int wm = (warp >> 2) * 32;
    const int wn = (warp & 3) * 32;
    const int bm = blockIdx.x * 64;
    const unsigned aBase = (unsigned)__cvta_generic_to_shared(As);
    const unsigned bBase = (unsigned)__cvta_generic_to_shared(Bs);
    const int nk = KW >> 4;

    Frag F = {};

    load_A(A, KW, bm, aBase, t, 0, 0);
    load_B(Wp, KW, 0, bBase, t, 0, 0);
    asm volatile("cp.async.commit_group;" ::: "memory");
    load_A(A, KW, bm, aBase, t, 1, 1);
    load_B(Wp, KW, 0, bBase, t, 1, 1);
    asm volatile("cp.async.commit_group;" ::: "memory");

    for (int kt = 0; kt < nk; kt++) {
        asm volatile("cp.async.wait_group 1;" ::: "memory");
        __syncthreads();

        int pf = kt + 2;
        if (pf < nk) {
            load_A(A, KW, bm, aBase, t, pf % SSTG, pf);
            load_B(Wp, KW, 0, bBase, t, pf % SSTG, pf);
        }
        asm volatile("cp.async.commit_group;" ::: "memory");

        tile_compute(aBase + (kt % SSTG) * ASTG * 4,
                     bBase + (kt % SSTG) * BSTG * 4, lane, wm, wn, F);
    }

    const int r = lane >> 2, cc = lane & 3;
#pragma unroll
    for (int mt = 0; mt < 2; mt++) {
        float p0 = 0.f, p1 = 0.f;
#pragma unroll
        for (int nt = 0; nt < 4; nt++) {
            int col = wn + nt * 8 + 2 * cc;
            float b0 = bias[col], b1 = bias[col + 1];
            float w0 = outW[col], w1 = outW[col + 1];
            p0 += fmaxf(F.acc[mt][nt][0] + b0, 0.f) * w0
                + fmaxf(F.acc[mt][nt][1] + b1, 0.f) * w1;
            p1 += fmaxf(F.acc[mt][nt][2] + b0, 0.f) * w0
                + fmaxf(F.acc[mt][nt][3] + b1, 0.f) * w1;
        }
        p0 += __shfl_xor_sync(0xffffffffu, p0, 1);
        p0 += __shfl_xor_sync(0xffffffffu, p0, 2);
        p1 += __shfl_xor_sync(0xffffffffu, p1, 1);
        p1 += __shfl_xor_sync(0xffffffffu, p1, 2);
        if (cc == 0) {
            red[wm + mt * 16 + r][warp & 3] = p0;
            red[wm + mt * 16 + r + 8][warp & 3] = p1;
        }
    }
    __syncthreads();
    if (t < 64) {
        float s = red[t][0] + red[t][1] + red[t][2] + red[t][3];
        float x = s + outB[0] + g_li[bm + t];
        out[bm + t] = 1.f / (1.f + expf(-x));
    }
}

// ---------------------------------------------------------------------------
extern "C" void kernel_launch(void* const* d_in, const int* in_sizes, int n_in,
                              void* d_out, int out_size)
{
    const int*   feat_ids  = (const int*)  d_in[0];
    const float* feat_vals = (const float*)d_in[1];
    const float* FM_W      = (const float*)d_in[2];
    const float* FM_V      = (const float*)d_in[3];
    const float* FM_B      = (const float*)d_in[4];
    const float* emb       = (const float*)d_in[5];
    const float* W0        = (const float*)d_in[6];
    const float* B0        = (const float*)d_in[7];
    const float* W1        = (const float*)d_in[8];
    const float* B1        = (const float*)d_in[9];
    const float* W2        = (const float*)d_in[10];
    const float* B2        = (const float*)d_in[11];
    const float* outW      = (const float*)d_in[12];
    const float* outB      = (const float*)d_in[13];
    float* out = (float*)d_out;

    int B = in_sizes[0] / FIELD;
    if (B > MAXB) B = MAXB;

    unsigned *h0, *h1, *h2, *w0p, *w1p, *w2p;
    cudaGetSymbolAddress((void**)&h0, g_h0);
    cudaGetSymbolAddress((void**)&h1, g_h1);
    cudaGetSymbolAddress((void**)&h2, g_h2);
    cudaGetSymbolAddress((void**)&w0p, g_w0p);
    cudaGetSymbolAddress((void**)&w1p, g_w1p);
    cudaGetSymbolAddress((void**)&w2p, g_w2p);

    int gB = (B * 40 + 255) / 256;
    int liB = (B + 31) / 32;

    gather_k<<<gB, 256>>>(feat_ids, emb, B);
    lipack_k<<<liB + PACK_BLKS, 256>>>(feat_ids, feat_vals, FM_W, FM_V, FM_B,
                                       W0, W1, W2, B, liB);

    gemm_mid<<<dim3(D1 / 128, B / 64), 256>>>(h0, w0p, B0, h1, D1, KW0);
    gemm_mid<<<dim3(D2 / 128, B / 64), 256>>>(h1, w1p, B1, h2, D2, KW1);
    gemm_last_head<<<B / 64, 256>>>(h2, w2p, B2, outW, outB, out, KW2);
}